// round 7
// baseline (speedup 1.0000x reference)
#include <cuda_runtime.h>

// PartialDataLoss: directional Chamfer (template -> scan) with threshold 0.1.
// Only scan points within sqrt(0.1)=0.3163 of a template point can matter, so
// bin scan points into a 32^3 grid (cell 0.32 >= 0.3163) and search only the
// 3x3x3 neighborhood. Coordinates are clamped into [-5.12,5.12); clamping is
// 1-Lipschitz so true distance <= 0.3163 implies clamped cell delta <= 1 per
// dim: the neighborhood search is exact, and distances use true coordinates.
//
// d2 = |t|^2 + (|s|^2 - 2 t.s); sorted points packed as (-2x,-2y,-2z,|s|^2).

#define GDIM     32
#define NCELLS   (GDIM * GDIM * GDIM)
#define GMIN     (-5.12f)
#define INV_CELL 3.125f          // 1/0.32, exact in fp32
#define THRESH   0.1f

#define N_MAX    65536
#define M_MAX    8192
#define QBLOCK   256
#define QWARPS   (QBLOCK / 32)
#define QB_MAX   ((M_MAX + QWARPS - 1) / QWARPS)

__device__ int    g_count[NCELLS];
__device__ int    g_start[NCELLS + 1];
__device__ int    g_cursor[NCELLS];
__device__ float4 g_sorted[N_MAX];
__device__ float  g_blocksum[QB_MAX];

__device__ __forceinline__ int clamp_cell(float v) {
    int c = __float2int_rd((v - GMIN) * INV_CELL);
    return max(0, min(GDIM - 1, c));
}

__global__ void zero_kernel() {
    int i = blockIdx.x * blockDim.x + threadIdx.x;
    if (i < NCELLS) g_count[i] = 0;
}

__global__ void count_kernel(const float* __restrict__ scan, int N) {
    int i = blockIdx.x * blockDim.x + threadIdx.x;
    if (i < N) {
        int cx = clamp_cell(scan[3 * i + 0]);
        int cy = clamp_cell(scan[3 * i + 1]);
        int cz = clamp_cell(scan[3 * i + 2]);
        atomicAdd(&g_count[(cx * GDIM + cy) * GDIM + cz], 1);
    }
}

// Exclusive prefix sum over NCELLS counts; one CTA of 1024 threads, 32 cells each.
__global__ void __launch_bounds__(1024) scan_kernel() {
    const int tid  = threadIdx.x;
    const int base = tid * 32;
    int vals[32];
    int run = 0;
#pragma unroll
    for (int k = 0; k < 32; k++) {
        int t = g_count[base + k];
        vals[k] = run;                 // local exclusive
        run += t;
    }
    const int lane = tid & 31, wid = tid >> 5;
    int v = run;                        // inclusive warp scan of thread totals
#pragma unroll
    for (int o = 1; o < 32; o <<= 1) {
        int n = __shfl_up_sync(0xFFFFFFFFu, v, o);
        if (lane >= o) v += n;
    }
    __shared__ int wtot[32];
    if (lane == 31) wtot[wid] = v;
    __syncthreads();
    if (wid == 0) {
        int w = wtot[lane];
#pragma unroll
        for (int o = 1; o < 32; o <<= 1) {
            int n = __shfl_up_sync(0xFFFFFFFFu, w, o);
            if (lane >= o) w += n;
        }
        wtot[lane] = w;                 // inclusive per-warp totals
    }
    __syncthreads();
    const int offset = (v - run) + (wid > 0 ? wtot[wid - 1] : 0);
#pragma unroll
    for (int k = 0; k < 32; k++) {
        int s = vals[k] + offset;
        g_start[base + k]  = s;
        g_cursor[base + k] = s;
    }
    if (tid == 1023) g_start[NCELLS] = offset + run;
}

__global__ void scatter_kernel(const float* __restrict__ scan, int N) {
    int i = blockIdx.x * blockDim.x + threadIdx.x;
    if (i < N) {
        float x = scan[3 * i + 0], y = scan[3 * i + 1], z = scan[3 * i + 2];
        int c = (clamp_cell(x) * GDIM + clamp_cell(y)) * GDIM + clamp_cell(z);
        int pos = atomicAdd(&g_cursor[c], 1);
        g_sorted[pos] = make_float4(-2.f * x, -2.f * y, -2.f * z,
                                    fmaf(x, x, fmaf(y, y, z * z)));
    }
}

// One warp per template point: exact min over the 3x3x3 cell neighborhood
// (z-contiguous cells merged into one [s,e) range per (x,y) row -> 9 ranges).
__global__ void __launch_bounds__(QBLOCK)
query_kernel(const float* __restrict__ tmpl, int M) {
    const int gw   = blockIdx.x * QWARPS + (threadIdx.x >> 5);
    const int lane = threadIdx.x & 31;

    float contrib = 0.0f;
    if (gw < M) {
        const float tx = __ldg(&tmpl[3 * gw + 0]);
        const float ty = __ldg(&tmpl[3 * gw + 1]);
        const float tz = __ldg(&tmpl[3 * gw + 2]);
        const float tsq = fmaf(tx, tx, fmaf(ty, ty, tz * tz));

        const int cx = clamp_cell(tx), cy = clamp_cell(ty), cz = clamp_cell(tz);
        const int xlo = max(cx - 1, 0), xhi = min(cx + 1, GDIM - 1);
        const int ylo = max(cy - 1, 0), yhi = min(cy + 1, GDIM - 1);
        const int zlo = max(cz - 1, 0), zhi = min(cz + 1, GDIM - 1);

        float mn = __int_as_float(0x7f800000);
        for (int xx = xlo; xx <= xhi; xx++) {
            for (int yy = ylo; yy <= yhi; yy++) {
                const int row = (xx * GDIM + yy) * GDIM;
                const int s = g_start[row + zlo];
                const int e = g_start[row + zhi + 1];
                for (int i = s + lane; i < e; i += 32) {
                    const float4 p = g_sorted[i];
                    float a = fmaf(p.x, tx, p.w);
                    a = fmaf(p.y, ty, a);
                    a = fmaf(p.z, tz, a);
                    mn = fminf(mn, a);
                }
            }
        }
#pragma unroll
        for (int o = 16; o > 0; o >>= 1)
            mn = fminf(mn, __shfl_xor_sync(0xFFFFFFFFu, mn, o));
        const float d2 = mn + tsq;
        if (d2 < THRESH) contrib = d2;
    }

    __shared__ float ws[QWARPS];
    if (lane == 0) ws[threadIdx.x >> 5] = contrib;
    __syncthreads();
    if (threadIdx.x == 0) {
        float s = 0.0f;
#pragma unroll
        for (int k = 0; k < QWARPS; k++) s += ws[k];   // fixed order
        g_blocksum[blockIdx.x] = s;
    }
}

__global__ void reduce2_kernel(float* __restrict__ out, int nblocks) {
    const int lane = threadIdx.x;
    float s = 0.0f;
    for (int b = lane; b < nblocks; b += 32)   // fixed strided partition
        s += g_blocksum[b];
#pragma unroll
    for (int o = 16; o > 0; o >>= 1)
        s += __shfl_down_sync(0xFFFFFFFFu, s, o);
    if (lane == 0) out[0] = s;
}

extern "C" void kernel_launch(void* const* d_in, const int* in_sizes, int n_in,
                              void* d_out, int out_size) {
    const float* scan = (const float*)d_in[0];
    const float* tmpl = (const float*)d_in[1];
    const int N = in_sizes[0] / 3;
    const int M = in_sizes[1] / 3;

    zero_kernel<<<(NCELLS + 1023) / 1024, 1024>>>();
    count_kernel<<<(N + 255) / 256, 256>>>(scan, N);
    scan_kernel<<<1, 1024>>>();
    scatter_kernel<<<(N + 255) / 256, 256>>>(scan, N);

    const int qblocks = (M + QWARPS - 1) / QWARPS;
    query_kernel<<<qblocks, QBLOCK>>>(tmpl, M);
    reduce2_kernel<<<1, 32>>>((float*)d_out, qblocks);
}

// round 8
// speedup vs baseline: 1.1965x; 1.1965x over previous
#include <cuda_runtime.h>

// PartialDataLoss: directional Chamfer (template -> scan) with threshold 0.1.
// Scan points binned into a 32^3 grid (cell 0.32 >= sqrt(0.1)=0.3163); exact
// 3x3x3 neighborhood search. Clamping to [-5.12,5.12) is 1-Lipschitz so the
// neighborhood is exact; distances always use true coordinates.
//
// d2 = |t|^2 + (|s|^2 - 2 t.s); binned points packed as (-2x,-2y,-2z,|s|^2).

#define GDIM     32
#define NCELLS   (GDIM * GDIM * GDIM)
#define GMIN     (-5.12f)
#define INV_CELL 3.125f          // 1/0.32, exact in fp32
#define THRESH   0.1f

#define N_MAX    65536
#define M_MAX    8192
#define QBLOCK   128             // 4 warps/CTA -> ~1723 CTAs -> ~46 warps/SM
#define QWARPS   (QBLOCK / 32)
#define QB_MAX   ((M_MAX + QWARPS - 1) / QWARPS)

__device__ int    g_count[NCELLS];
__device__ int    g_start[NCELLS + 1];
__device__ int    g_cursor[NCELLS];
__device__ float4 g_sorted[N_MAX];
__device__ float  g_blocksum[QB_MAX];

__device__ __forceinline__ int clamp_cell(float v) {
    int c = __float2int_rd((v - GMIN) * INV_CELL);
    return max(0, min(GDIM - 1, c));
}

__global__ void zero_kernel() {
    int i = blockIdx.x * blockDim.x + threadIdx.x;
    if (i < NCELLS) g_count[i] = 0;
}

__global__ void count_kernel(const float* __restrict__ scan, int N) {
    int i = blockIdx.x * blockDim.x + threadIdx.x;
    if (i < N) {
        int cx = clamp_cell(scan[3 * i + 0]);
        int cy = clamp_cell(scan[3 * i + 1]);
        int cz = clamp_cell(scan[3 * i + 2]);
        atomicAdd(&g_count[(cx * GDIM + cy) * GDIM + cz], 1);
    }
}

// Exclusive prefix sum over NCELLS counts; one CTA of 1024 threads, 32 cells each.
__global__ void __launch_bounds__(1024) scan_kernel() {
    const int tid  = threadIdx.x;
    const int base = tid * 32;
    int vals[32];
    int run = 0;
#pragma unroll
    for (int k = 0; k < 32; k++) {
        int t = g_count[base + k];
        vals[k] = run;                 // local exclusive
        run += t;
    }
    const int lane = tid & 31, wid = tid >> 5;
    int v = run;                        // inclusive warp scan of thread totals
#pragma unroll
    for (int o = 1; o < 32; o <<= 1) {
        int n = __shfl_up_sync(0xFFFFFFFFu, v, o);
        if (lane >= o) v += n;
    }
    __shared__ int wtot[32];
    if (lane == 31) wtot[wid] = v;
    __syncthreads();
    if (wid == 0) {
        int w = wtot[lane];
#pragma unroll
        for (int o = 1; o < 32; o <<= 1) {
            int n = __shfl_up_sync(0xFFFFFFFFu, w, o);
            if (lane >= o) w += n;
        }
        wtot[lane] = w;                 // inclusive per-warp totals
    }
    __syncthreads();
    const int offset = (v - run) + (wid > 0 ? wtot[wid - 1] : 0);
#pragma unroll
    for (int k = 0; k < 32; k++) {
        int s = vals[k] + offset;
        g_start[base + k]  = s;
        g_cursor[base + k] = s;
    }
    if (tid == 1023) g_start[NCELLS] = offset + run;
}

__global__ void scatter_kernel(const float* __restrict__ scan, int N) {
    int i = blockIdx.x * blockDim.x + threadIdx.x;
    if (i < N) {
        float x = scan[3 * i + 0], y = scan[3 * i + 1], z = scan[3 * i + 2];
        int c = (clamp_cell(x) * GDIM + clamp_cell(y)) * GDIM + clamp_cell(z);
        int pos = atomicAdd(&g_cursor[c], 1);
        g_sorted[pos] = make_float4(-2.f * x, -2.f * y, -2.f * z,
                                    fmaf(x, x, fmaf(y, y, z * z)));
    }
}

// One warp per template point; 9 z-merged ranges; 4-way unrolled gather loop
// (4 independent loads + 4 independent min accumulators -> MLP=4).
__global__ void __launch_bounds__(QBLOCK)
query_kernel(const float* __restrict__ tmpl, int M) {
    const int gw   = blockIdx.x * QWARPS + (threadIdx.x >> 5);
    const int lane = threadIdx.x & 31;

    float contrib = 0.0f;
    if (gw < M) {
        const float tx = __ldg(&tmpl[3 * gw + 0]);
        const float ty = __ldg(&tmpl[3 * gw + 1]);
        const float tz = __ldg(&tmpl[3 * gw + 2]);
        const float tsq = fmaf(tx, tx, fmaf(ty, ty, tz * tz));

        const int cx = clamp_cell(tx), cy = clamp_cell(ty), cz = clamp_cell(tz);
        const int xlo = max(cx - 1, 0), xhi = min(cx + 1, GDIM - 1);
        const int ylo = max(cy - 1, 0), yhi = min(cy + 1, GDIM - 1);
        const int zlo = max(cz - 1, 0), zhi = min(cz + 1, GDIM - 1);

        const float inf = __int_as_float(0x7f800000);
        float mn0 = inf, mn1 = inf, mn2 = inf, mn3 = inf;

        for (int xx = xlo; xx <= xhi; xx++) {
            for (int yy = ylo; yy <= yhi; yy++) {
                const int row = (xx * GDIM + yy) * GDIM;
                const int s = __ldg(&g_start[row + zlo]);
                const int e = __ldg(&g_start[row + zhi + 1]);
                for (int i = s + lane; i < e; i += 128) {
                    const int i1 = i + 32, i2 = i + 64, i3 = i + 96;
                    // 4 independent predicated loads issue back-to-back.
                    float4 p0 = g_sorted[i];
                    float4 p1, p2, p3;
                    if (i1 < e) p1 = g_sorted[i1];
                    if (i2 < e) p2 = g_sorted[i2];
                    if (i3 < e) p3 = g_sorted[i3];
                    {
                        float a = fmaf(p0.x, tx, p0.w);
                        a = fmaf(p0.y, ty, a);
                        a = fmaf(p0.z, tz, a);
                        mn0 = fminf(mn0, a);
                    }
                    if (i1 < e) {
                        float a = fmaf(p1.x, tx, p1.w);
                        a = fmaf(p1.y, ty, a);
                        a = fmaf(p1.z, tz, a);
                        mn1 = fminf(mn1, a);
                    }
                    if (i2 < e) {
                        float a = fmaf(p2.x, tx, p2.w);
                        a = fmaf(p2.y, ty, a);
                        a = fmaf(p2.z, tz, a);
                        mn2 = fminf(mn2, a);
                    }
                    if (i3 < e) {
                        float a = fmaf(p3.x, tx, p3.w);
                        a = fmaf(p3.y, ty, a);
                        a = fmaf(p3.z, tz, a);
                        mn3 = fminf(mn3, a);
                    }
                }
            }
        }
        float mn = fminf(fminf(mn0, mn1), fminf(mn2, mn3));
#pragma unroll
        for (int o = 16; o > 0; o >>= 1)
            mn = fminf(mn, __shfl_xor_sync(0xFFFFFFFFu, mn, o));
        const float d2 = mn + tsq;
        if (d2 < THRESH) contrib = d2;
    }

    __shared__ float ws[QWARPS];
    if (lane == 0) ws[threadIdx.x >> 5] = contrib;
    __syncthreads();
    if (threadIdx.x == 0) {
        float s = 0.0f;
#pragma unroll
        for (int k = 0; k < QWARPS; k++) s += ws[k];   // fixed order
        g_blocksum[blockIdx.x] = s;
    }
}

__global__ void reduce2_kernel(float* __restrict__ out, int nblocks) {
    const int lane = threadIdx.x;
    float s = 0.0f;
    for (int b = lane; b < nblocks; b += 32)   // fixed strided partition
        s += g_blocksum[b];
#pragma unroll
    for (int o = 16; o > 0; o >>= 1)
        s += __shfl_down_sync(0xFFFFFFFFu, s, o);
    if (lane == 0) out[0] = s;
}

extern "C" void kernel_launch(void* const* d_in, const int* in_sizes, int n_in,
                              void* d_out, int out_size) {
    const float* scan = (const float*)d_in[0];
    const float* tmpl = (const float*)d_in[1];
    const int N = in_sizes[0] / 3;
    const int M = in_sizes[1] / 3;

    zero_kernel<<<(NCELLS + 1023) / 1024, 1024>>>();
    count_kernel<<<(N + 255) / 256, 256>>>(scan, N);
    scan_kernel<<<1, 1024>>>();
    scatter_kernel<<<(N + 255) / 256, 256>>>(scan, N);

    const int qblocks = (M + QWARPS - 1) / QWARPS;
    query_kernel<<<qblocks, QBLOCK>>>(tmpl, M);
    reduce2_kernel<<<1, 32>>>((float*)d_out, qblocks);
}

// round 9
// speedup vs baseline: 2.4745x; 2.0681x over previous
#include <cuda_runtime.h>

// PartialDataLoss: directional Chamfer (template -> scan) with threshold 0.1.
// Scan points binned into a 32^3 grid (cell 0.32 >= sqrt(0.1)=0.3163); exact
// 3x3x3 neighborhood search. Clamping to [-5.12,5.12) is 1-Lipschitz so the
// neighborhood is exact; distances always use true coordinates.
//
// d2 = |t|^2 + (|s|^2 - 2 t.s); binned points packed as (-2x,-2y,-2z,|s|^2).

#define GDIM     32
#define NCELLS   (GDIM * GDIM * GDIM)
#define GMIN     (-5.12f)
#define INV_CELL 3.125f          // 1/0.32, exact in fp32
#define THRESH   0.1f

#define N_MAX    65536
#define M_MAX    8192
#define QBLOCK   128             // 4 warps/CTA -> ~1723 CTAs -> high residency
#define QWARPS   (QBLOCK / 32)
#define QB_MAX   ((M_MAX + QWARPS - 1) / QWARPS)

__device__ int    g_count[NCELLS];
__device__ int    g_start[NCELLS + 4];   // +pad so int4 stores stay in bounds
__device__ int    g_cursor[NCELLS];
__device__ float4 g_sorted[N_MAX];
__device__ float  g_blocksum[QB_MAX];

__device__ __forceinline__ int clamp_cell(float v) {
    int c = __float2int_rd((v - GMIN) * INV_CELL);
    return max(0, min(GDIM - 1, c));
}

__global__ void zero_kernel() {
    int i = blockIdx.x * blockDim.x + threadIdx.x;
    if (i < NCELLS / 4)
        reinterpret_cast<int4*>(g_count)[i] = make_int4(0, 0, 0, 0);
}

__global__ void count_kernel(const float* __restrict__ scan, int N) {
    int i = blockIdx.x * blockDim.x + threadIdx.x;
    if (i < N) {
        int cx = clamp_cell(scan[3 * i + 0]);
        int cy = clamp_cell(scan[3 * i + 1]);
        int cz = clamp_cell(scan[3 * i + 2]);
        atomicAdd(&g_count[(cx * GDIM + cy) * GDIM + cz], 1);
    }
}

// Exclusive prefix sum over NCELLS counts; one CTA of 1024 threads, 32 cells
// each. All global traffic is int4-vectorized (8 lines/warp-instr instead of
// 32) -- the scalar version was single-SM L1-wavefront bound (~30us).
__global__ void __launch_bounds__(1024) scan_kernel() {
    const int tid  = threadIdx.x;
    const int base = tid * 32;

    int a[32];
    {
        const int4* c4 = reinterpret_cast<const int4*>(g_count);
#pragma unroll
        for (int k = 0; k < 8; k++) {
            int4 v = c4[tid * 8 + k];
            a[4 * k + 0] = v.x; a[4 * k + 1] = v.y;
            a[4 * k + 2] = v.z; a[4 * k + 3] = v.w;
        }
    }

    int run = 0;
#pragma unroll
    for (int k = 0; k < 32; k++) {
        int t = a[k];
        a[k] = run;                    // local exclusive
        run += t;
    }

    const int lane = tid & 31, wid = tid >> 5;
    int v = run;                        // inclusive warp scan of thread totals
#pragma unroll
    for (int o = 1; o < 32; o <<= 1) {
        int n = __shfl_up_sync(0xFFFFFFFFu, v, o);
        if (lane >= o) v += n;
    }
    __shared__ int wtot[32];
    if (lane == 31) wtot[wid] = v;
    __syncthreads();
    if (wid == 0) {
        int w = wtot[lane];
#pragma unroll
        for (int o = 1; o < 32; o <<= 1) {
            int n = __shfl_up_sync(0xFFFFFFFFu, w, o);
            if (lane >= o) w += n;
        }
        wtot[lane] = w;                 // inclusive per-warp totals
    }
    __syncthreads();
    const int offset = (v - run) + (wid > 0 ? wtot[wid - 1] : 0);

    {
        int4* s4 = reinterpret_cast<int4*>(g_start);
        int4* u4 = reinterpret_cast<int4*>(g_cursor);
#pragma unroll
        for (int k = 0; k < 8; k++) {
            int4 o4 = make_int4(a[4 * k + 0] + offset, a[4 * k + 1] + offset,
                                a[4 * k + 2] + offset, a[4 * k + 3] + offset);
            s4[tid * 8 + k] = o4;
            u4[tid * 8 + k] = o4;
        }
    }
    if (tid == 1023) g_start[NCELLS] = offset + run;
    (void)base;
}

__global__ void scatter_kernel(const float* __restrict__ scan, int N) {
    int i = blockIdx.x * blockDim.x + threadIdx.x;
    if (i < N) {
        float x = scan[3 * i + 0], y = scan[3 * i + 1], z = scan[3 * i + 2];
        int c = (clamp_cell(x) * GDIM + clamp_cell(y)) * GDIM + clamp_cell(z);
        int pos = atomicAdd(&g_cursor[c], 1);
        g_sorted[pos] = make_float4(-2.f * x, -2.f * y, -2.f * z,
                                    fmaf(x, x, fmaf(y, y, z * z)));
    }
}

// One warp per template point; 9 z-merged ranges; 4-way unrolled gather loop
// (4 independent loads + 4 independent min accumulators -> MLP=4).
__global__ void __launch_bounds__(QBLOCK)
query_kernel(const float* __restrict__ tmpl, int M) {
    const int gw   = blockIdx.x * QWARPS + (threadIdx.x >> 5);
    const int lane = threadIdx.x & 31;

    float contrib = 0.0f;
    if (gw < M) {
        const float tx = __ldg(&tmpl[3 * gw + 0]);
        const float ty = __ldg(&tmpl[3 * gw + 1]);
        const float tz = __ldg(&tmpl[3 * gw + 2]);
        const float tsq = fmaf(tx, tx, fmaf(ty, ty, tz * tz));

        const int cx = clamp_cell(tx), cy = clamp_cell(ty), cz = clamp_cell(tz);
        const int xlo = max(cx - 1, 0), xhi = min(cx + 1, GDIM - 1);
        const int ylo = max(cy - 1, 0), yhi = min(cy + 1, GDIM - 1);
        const int zlo = max(cz - 1, 0), zhi = min(cz + 1, GDIM - 1);

        const float inf = __int_as_float(0x7f800000);
        float mn0 = inf, mn1 = inf, mn2 = inf, mn3 = inf;

        for (int xx = xlo; xx <= xhi; xx++) {
            for (int yy = ylo; yy <= yhi; yy++) {
                const int row = (xx * GDIM + yy) * GDIM;
                const int s = __ldg(&g_start[row + zlo]);
                const int e = __ldg(&g_start[row + zhi + 1]);
                for (int i = s + lane; i < e; i += 128) {
                    const int i1 = i + 32, i2 = i + 64, i3 = i + 96;
                    float4 p0 = g_sorted[i];
                    float4 p1, p2, p3;
                    if (i1 < e) p1 = g_sorted[i1];
                    if (i2 < e) p2 = g_sorted[i2];
                    if (i3 < e) p3 = g_sorted[i3];
                    {
                        float a = fmaf(p0.x, tx, p0.w);
                        a = fmaf(p0.y, ty, a);
                        a = fmaf(p0.z, tz, a);
                        mn0 = fminf(mn0, a);
                    }
                    if (i1 < e) {
                        float a = fmaf(p1.x, tx, p1.w);
                        a = fmaf(p1.y, ty, a);
                        a = fmaf(p1.z, tz, a);
                        mn1 = fminf(mn1, a);
                    }
                    if (i2 < e) {
                        float a = fmaf(p2.x, tx, p2.w);
                        a = fmaf(p2.y, ty, a);
                        a = fmaf(p2.z, tz, a);
                        mn2 = fminf(mn2, a);
                    }
                    if (i3 < e) {
                        float a = fmaf(p3.x, tx, p3.w);
                        a = fmaf(p3.y, ty, a);
                        a = fmaf(p3.z, tz, a);
                        mn3 = fminf(mn3, a);
                    }
                }
            }
        }
        float mn = fminf(fminf(mn0, mn1), fminf(mn2, mn3));
#pragma unroll
        for (int o = 16; o > 0; o >>= 1)
            mn = fminf(mn, __shfl_xor_sync(0xFFFFFFFFu, mn, o));
        const float d2 = mn + tsq;
        if (d2 < THRESH) contrib = d2;
    }

    __shared__ float ws[QWARPS];
    if (lane == 0) ws[threadIdx.x >> 5] = contrib;
    __syncthreads();
    if (threadIdx.x == 0) {
        float s = 0.0f;
#pragma unroll
        for (int k = 0; k < QWARPS; k++) s += ws[k];   // fixed order
        g_blocksum[blockIdx.x] = s;
    }
}

__global__ void reduce2_kernel(float* __restrict__ out, int nblocks) {
    const int lane = threadIdx.x;
    float s = 0.0f;
    for (int b = lane; b < nblocks; b += 32)   // fixed strided partition
        s += g_blocksum[b];
#pragma unroll
    for (int o = 16; o > 0; o >>= 1)
        s += __shfl_down_sync(0xFFFFFFFFu, s, o);
    if (lane == 0) out[0] = s;
}

extern "C" void kernel_launch(void* const* d_in, const int* in_sizes, int n_in,
                              void* d_out, int out_size) {
    const float* scan = (const float*)d_in[0];
    const float* tmpl = (const float*)d_in[1];
    const int N = in_sizes[0] / 3;
    const int M = in_sizes[1] / 3;

    zero_kernel<<<(NCELLS / 4 + 255) / 256, 256>>>();
    count_kernel<<<(N + 255) / 256, 256>>>(scan, N);
    scan_kernel<<<1, 1024>>>();
    scatter_kernel<<<(N + 255) / 256, 256>>>(scan, N);

    const int qblocks = (M + QWARPS - 1) / QWARPS;
    query_kernel<<<qblocks, QBLOCK>>>(tmpl, M);
    reduce2_kernel<<<1, 32>>>((float*)d_out, qblocks);
}

// round 11
// speedup vs baseline: 3.3267x; 1.3444x over previous
#include <cuda_runtime.h>

// PartialDataLoss: directional Chamfer (template -> scan) with threshold 0.1.
// Scan points binned into a 32^3 grid (cell 0.32 >= sqrt(0.1)); exact 3x3x3
// neighborhood search with geometric row pruning. Clamping to [-5.12,5.12) is
// 1-Lipschitz; distances always use true coordinates. Slab lower bounds stay
// valid under clamping (outliers only enter boundary cells from the valid
// side; center rows use dx=0 explicitly).
//
// d2 = |t|^2 + (|s|^2 - 2 t.s); binned points packed as (-2x,-2y,-2z,|s|^2).
//
// 4 launches: count (atomic rank capture, UNSIGNED pack: cell<<17 reaches bit
// 31, so unpack must be a logical shift) -> scan (int4 prefix sum) ->
// scatter (atomic-free, re-zeroes g_count for next replay) ->
// query (row pruning + last-block ticket reduction, fixed-order sums).

#define GDIM     32
#define NCELLS   (GDIM * GDIM * GDIM)
#define GMIN     (-5.12f)
#define CELL     0.32f
#define INV_CELL 3.125f          // 1/0.32, exact in fp32
#define THRESH   0.1f

#define N_MAX    65536
#define M_MAX    8192
#define QBLOCK   128
#define QWARPS   (QBLOCK / 32)
#define QB_MAX   ((M_MAX + QWARPS - 1) / QWARPS)

__device__ int      g_count[NCELLS];      // zero at load; re-zeroed by scatter
__device__ int      g_start[NCELLS + 4];  // +pad for int4 stores
__device__ unsigned g_rank[N_MAX];        // (cell << 17) | rank  (logical shifts!)
__device__ float4   g_sorted[N_MAX];
__device__ float    g_blocksum[QB_MAX];
__device__ int      g_ticket;             // zero at load; reset by last block

__device__ __forceinline__ int clamp_cell(float v) {
    int c = __float2int_rd((v - GMIN) * INV_CELL);
    return max(0, min(GDIM - 1, c));
}

__global__ void count_kernel(const float* __restrict__ scan, int N) {
    int i = blockIdx.x * blockDim.x + threadIdx.x;
    if (i < N) {
        int cx = clamp_cell(scan[3 * i + 0]);
        int cy = clamp_cell(scan[3 * i + 1]);
        int cz = clamp_cell(scan[3 * i + 2]);
        unsigned c = (unsigned)((cx * GDIM + cy) * GDIM + cz);
        unsigned pos = (unsigned)atomicAdd(&g_count[c], 1);
        g_rank[i] = (c << 17) | pos;
    }
}

// Exclusive prefix sum over NCELLS counts; one CTA, int4-vectorized traffic.
__global__ void __launch_bounds__(1024) scan_kernel() {
    const int tid = threadIdx.x;

    int a[32];
    {
        const int4* c4 = reinterpret_cast<const int4*>(g_count);
#pragma unroll
        for (int k = 0; k < 8; k++) {
            int4 v = c4[tid * 8 + k];
            a[4 * k + 0] = v.x; a[4 * k + 1] = v.y;
            a[4 * k + 2] = v.z; a[4 * k + 3] = v.w;
        }
    }

    int run = 0;
#pragma unroll
    for (int k = 0; k < 32; k++) {
        int t = a[k];
        a[k] = run;
        run += t;
    }

    const int lane = tid & 31, wid = tid >> 5;
    int v = run;
#pragma unroll
    for (int o = 1; o < 32; o <<= 1) {
        int n = __shfl_up_sync(0xFFFFFFFFu, v, o);
        if (lane >= o) v += n;
    }
    __shared__ int wtot[32];
    if (lane == 31) wtot[wid] = v;
    __syncthreads();
    if (wid == 0) {
        int w = wtot[lane];
#pragma unroll
        for (int o = 1; o < 32; o <<= 1) {
            int n = __shfl_up_sync(0xFFFFFFFFu, w, o);
            if (lane >= o) w += n;
        }
        wtot[lane] = w;
    }
    __syncthreads();
    const int offset = (v - run) + (wid > 0 ? wtot[wid - 1] : 0);

    {
        int4* s4 = reinterpret_cast<int4*>(g_start);
#pragma unroll
        for (int k = 0; k < 8; k++)
            s4[tid * 8 + k] = make_int4(a[4 * k + 0] + offset, a[4 * k + 1] + offset,
                                        a[4 * k + 2] + offset, a[4 * k + 3] + offset);
    }
    if (tid == 1023) g_start[NCELLS] = offset + run;
}

__global__ void scatter_kernel(const float* __restrict__ scan, int N) {
    int i = blockIdx.x * blockDim.x + threadIdx.x;
    if (i < N) {
        unsigned r = g_rank[i];
        int c   = (int)(r >> 17);          // logical shift: c in [0, 32767]
        int pos = (int)(r & 0x1FFFFu);
        float x = scan[3 * i + 0], y = scan[3 * i + 1], z = scan[3 * i + 2];
        g_sorted[g_start[c] + pos] = make_float4(-2.f * x, -2.f * y, -2.f * z,
                                                 fmaf(x, x, fmaf(y, y, z * z)));
    }
    if (i < NCELLS) g_count[i] = 0;   // ready for next graph replay (scan done)
}

// One warp per template point. Center z-row first; its warp-reduced min (plus
// THRESH cap) prunes the 8 remaining (x,y) rows by slab lower bound dx^2+dy^2.
__global__ void __launch_bounds__(QBLOCK)
query_kernel(const float* __restrict__ tmpl, int M, float* __restrict__ out) {
    const int wid  = threadIdx.x >> 5;
    const int gw   = blockIdx.x * QWARPS + wid;
    const int lane = threadIdx.x & 31;

    float contrib = 0.0f;
    if (gw < M) {
        const float tx = __ldg(&tmpl[3 * gw + 0]);
        const float ty = __ldg(&tmpl[3 * gw + 1]);
        const float tz = __ldg(&tmpl[3 * gw + 2]);
        const float tsq = fmaf(tx, tx, fmaf(ty, ty, tz * tz));

        const int cx = clamp_cell(tx), cy = clamp_cell(ty), cz = clamp_cell(tz);
        const int xlo = max(cx - 1, 0), xhi = min(cx + 1, GDIM - 1);
        const int ylo = max(cy - 1, 0), yhi = min(cy + 1, GDIM - 1);
        const int zlo = max(cz - 1, 0), zhi = min(cz + 1, GDIM - 1);

        const float inf = __int_as_float(0x7f800000);
        float mn0 = inf, mn1 = inf, mn2 = inf, mn3 = inf;

        // Row processor: min of (|s|^2 - 2 t.s) over [s,e), stride-128, MLP=4.
        auto do_row = [&](int s, int e) {
            for (int i = s + lane; i < e; i += 128) {
                const int i1 = i + 32, i2 = i + 64, i3 = i + 96;
                float4 p0 = g_sorted[i];
                float4 p1, p2, p3;
                if (i1 < e) p1 = g_sorted[i1];
                if (i2 < e) p2 = g_sorted[i2];
                if (i3 < e) p3 = g_sorted[i3];
                {
                    float a = fmaf(p0.x, tx, p0.w);
                    a = fmaf(p0.y, ty, a); a = fmaf(p0.z, tz, a);
                    mn0 = fminf(mn0, a);
                }
                if (i1 < e) {
                    float a = fmaf(p1.x, tx, p1.w);
                    a = fmaf(p1.y, ty, a); a = fmaf(p1.z, tz, a);
                    mn1 = fminf(mn1, a);
                }
                if (i2 < e) {
                    float a = fmaf(p2.x, tx, p2.w);
                    a = fmaf(p2.y, ty, a); a = fmaf(p2.z, tz, a);
                    mn2 = fminf(mn2, a);
                }
                if (i3 < e) {
                    float a = fmaf(p3.x, tx, p3.w);
                    a = fmaf(p3.y, ty, a); a = fmaf(p3.z, tz, a);
                    mn3 = fminf(mn3, a);
                }
            }
        };

        // Center row first.
        {
            const int row = (cx * GDIM + cy) * GDIM;
            do_row(__ldg(&g_start[row + zlo]), __ldg(&g_start[row + zhi + 1]));
        }
        // Warp-reduced bound from the center row (actual-d2 space), capped by THRESH.
        float cm = fminf(fminf(mn0, mn1), fminf(mn2, mn3));
#pragma unroll
        for (int o = 16; o > 0; o >>= 1)
            cm = fminf(cm, __shfl_xor_sync(0xFFFFFFFFu, cm, o));
        const float runb = fminf(THRESH, cm + tsq);

        for (int xx = xlo; xx <= xhi; xx++) {
            const float ax = GMIN + xx * CELL, bx = ax + CELL;
            const float dx = (xx == cx) ? 0.f
                             : fmaxf(0.f, fmaxf(ax - tx, tx - bx));
            for (int yy = ylo; yy <= yhi; yy++) {
                if (xx == cx && yy == cy) continue;   // already done
                const float ay = GMIN + yy * CELL, by = ay + CELL;
                const float dy = (yy == cy) ? 0.f
                                 : fmaxf(0.f, fmaxf(ay - ty, ty - by));
                if (fmaf(dx, dx, dy * dy) >= runb) continue;  // provably irrelevant
                const int row = (xx * GDIM + yy) * GDIM;
                do_row(__ldg(&g_start[row + zlo]), __ldg(&g_start[row + zhi + 1]));
            }
        }

        float mn = fminf(fminf(mn0, mn1), fminf(mn2, mn3));
#pragma unroll
        for (int o = 16; o > 0; o >>= 1)
            mn = fminf(mn, __shfl_xor_sync(0xFFFFFFFFu, mn, o));
        const float d2 = mn + tsq;
        if (d2 < THRESH) contrib = d2;
    }

    __shared__ float ws[QWARPS];
    __shared__ bool amlast;
    if (lane == 0) ws[wid] = contrib;
    __syncthreads();
    if (threadIdx.x == 0) {
        float s = 0.0f;
#pragma unroll
        for (int k = 0; k < QWARPS; k++) s += ws[k];   // fixed order
        g_blocksum[blockIdx.x] = s;
        __threadfence();
        int t = atomicAdd(&g_ticket, 1);
        amlast = (t == (int)gridDim.x - 1);
    }
    __syncthreads();

    if (amlast) {   // deterministic final reduction by the last-arriving block
        __threadfence();
        float s = 0.0f;
        for (int b = threadIdx.x; b < (int)gridDim.x; b += QBLOCK)
            s += g_blocksum[b];                        // fixed strided partition
#pragma unroll
        for (int o = 16; o > 0; o >>= 1)
            s += __shfl_down_sync(0xFFFFFFFFu, s, o);
        if (lane == 0) ws[wid] = s;
        __syncthreads();
        if (threadIdx.x == 0) {
            float tot = 0.0f;
#pragma unroll
            for (int k = 0; k < QWARPS; k++) tot += ws[k];
            out[0] = tot;
            g_ticket = 0;                              // ready for next replay
        }
    }
}

extern "C" void kernel_launch(void* const* d_in, const int* in_sizes, int n_in,
                              void* d_out, int out_size) {
    const float* scan = (const float*)d_in[0];
    const float* tmpl = (const float*)d_in[1];
    const int N = in_sizes[0] / 3;
    const int M = in_sizes[1] / 3;

    count_kernel<<<(N + 255) / 256, 256>>>(scan, N);
    scan_kernel<<<1, 1024>>>();
    scatter_kernel<<<(N + 255) / 256, 256>>>(scan, N);

    const int qblocks = (M + QWARPS - 1) / QWARPS;
    query_kernel<<<qblocks, QBLOCK>>>(tmpl, M, (float*)d_out);
}